// round 4
// baseline (speedup 1.0000x reference)
#include <cuda_runtime.h>
#include <cuda_bf16.h>
#include <cstdint>

#define HGRID 768
#define WGRID 768
#define NMAX  200064   // 1563 * 128

// Scratch in __device__ globals (no allocation allowed).
__device__ int g_idx_map[HGRID * WGRID];
// h1/h2 as interleaved bf16 split planes: per row {128B hi, 128B lo}
__device__ __align__(16) unsigned char g_h1b[(size_t)NMAX * 256];
__device__ __align__(16) unsigned char g_h2b[(size_t)NMAX * 256];
// w2 B fragments: [tap][kc(4)][nt(8)][lane(32)] uint4 {bhi0,bhi1,blo0,blo1}
__device__ uint4 g_w2f[9 * 4 * 8 * 32];
// w3 B fragments: [cb(4)][kc(4)][nt(8)][lane(32)]
__device__ uint4 g_w3f[4 * 4 * 8 * 32];

// ---------------------------------------------------------------------------
__device__ __forceinline__ int coords_is64(const int* c) { return c[1] == 0; }
__device__ __forceinline__ int load_coord(const int* c, int is64, int i) {
    return is64 ? c[2 * i] : c[i];
}
__device__ __forceinline__ void bsplit2(float a, float b, uint32_t& hi, uint32_t& lo) {
    __nv_bfloat16 ah = __float2bfloat16(a);
    __nv_bfloat16 bh = __float2bfloat16(b);
    float ar = a - __bfloat162float(ah);
    float br = b - __bfloat162float(bh);
    __nv_bfloat162 h; h.x = ah; h.y = bh;
    __nv_bfloat162 l; l.x = __float2bfloat16(ar); l.y = __float2bfloat16(br);
    hi = *reinterpret_cast<uint32_t*>(&h);
    lo = *reinterpret_cast<uint32_t*>(&l);
}

// mma.sync m16n8k16 bf16 -> f32 accumulate
__device__ __forceinline__ void mma16816(float c[4], const uint32_t a[4],
                                         uint32_t b0, uint32_t b1) {
    asm volatile(
        "mma.sync.aligned.m16n8k16.row.col.f32.bf16.bf16.f32 "
        "{%0,%1,%2,%3}, {%4,%5,%6,%7}, {%8,%9}, {%0,%1,%2,%3};"
        : "+f"(c[0]), "+f"(c[1]), "+f"(c[2]), "+f"(c[3])
        : "r"(a[0]), "r"(a[1]), "r"(a[2]), "r"(a[3]), "r"(b0), "r"(b1));
}

// ---------------------------------------------------------------------------
__global__ void clear_map_kernel() {
    int i = blockIdx.x * blockDim.x + threadIdx.x;
    if (i < HGRID * WGRID) g_idx_map[i] = -1;
}
__global__ void scatter_map_kernel(const int* __restrict__ coords, int n) {
    int i = blockIdx.x * blockDim.x + threadIdx.x;
    int is64 = coords_is64(coords);
    if (i < n) g_idx_map[load_coord(coords, is64, i)] = i;
}

// w2 [9][64 k][64 n] -> per-lane B fragments (hi/lo bf16 split).
__global__ void prep_w2f_kernel(const float* __restrict__ w2) {
    int i = blockIdx.x * blockDim.x + threadIdx.x;
    if (i >= 9 * 4 * 8 * 32) return;
    int lane = i & 31, nt = (i >> 5) & 7, kc = (i >> 8) & 3, tap = i >> 10;
    int n  = nt * 8 + (lane >> 2);
    int k0 = kc * 16 + (lane & 3) * 2;
    uint32_t hi[2], lo[2];
#pragma unroll
    for (int j = 0; j < 2; ++j) {
        int k = k0 + j * 8;
        bsplit2(w2[tap * 4096 + k * 64 + n], w2[tap * 4096 + (k + 1) * 64 + n],
                hi[j], lo[j]);
    }
    g_w2f[i] = make_uint4(hi[0], hi[1], lo[0], lo[1]);
}

// w3 [64 k][256 n] -> per-lane B fragments per 64-col block cb.
__global__ void prep_w3f_kernel(const float* __restrict__ w3) {
    int i = blockIdx.x * blockDim.x + threadIdx.x;
    if (i >= 4 * 4 * 8 * 32) return;
    int lane = i & 31, nt = (i >> 5) & 7, kc = (i >> 8) & 3, cb = i >> 10;
    int n  = cb * 64 + nt * 8 + (lane >> 2);
    int k0 = kc * 16 + (lane & 3) * 2;
    uint32_t hi[2], lo[2];
#pragma unroll
    for (int j = 0; j < 2; ++j) {
        int k = k0 + j * 8;
        bsplit2(w3[k * 256 + n], w3[(k + 1) * 256 + n], hi[j], lo[j]);
    }
    g_w3f[i] = make_uint4(hi[0], hi[1], lo[0], lo[1]);
}

// ---------------------------------------------------------------------------
// FFMA micro-kernel (conv1)
template <int LDA>
__device__ __forceinline__ void mm32(const float* __restrict__ sA,
                                     const float* __restrict__ sB,
                                     int trow, int tcol, float acc[8][4]) {
#pragma unroll
    for (int k = 0; k < 32; ++k) {
        float4 b = *(const float4*)(sB + k * 64 + tcol);
#pragma unroll
        for (int i = 0; i < 8; ++i) {
            float a = sA[(trow + i) * LDA + k];
            acc[i][0] = fmaf(a, b.x, acc[i][0]);
            acc[i][1] = fmaf(a, b.y, acc[i][1]);
            acc[i][2] = fmaf(a, b.z, acc[i][2]);
            acc[i][3] = fmaf(a, b.w, acc[i][3]);
        }
    }
}

// conv1: h1 = relu((feats @ w1) * s1 + b1) -> bf16 hi/lo planes
__global__ void __launch_bounds__(256) conv1_kernel(
    const float* __restrict__ feats, const float* __restrict__ w1,
    const float* __restrict__ s1, const float* __restrict__ b1, int n)
{
    __shared__ __align__(16) float sA[128 * 33];
    __shared__ __align__(16) float sB[32 * 64];
    const int tid = threadIdx.x;
    const int site0 = blockIdx.x * 128;
    const int trow = (tid >> 4) << 3;
    const int tcol = (tid & 15) << 2;

    float acc[8][4];
#pragma unroll
    for (int i = 0; i < 8; ++i)
#pragma unroll
        for (int j = 0; j < 4; ++j) acc[i][j] = 0.f;

#pragma unroll 1
    for (int k0 = 0; k0 < 256; k0 += 32) {
#pragma unroll
        for (int l = 0; l < 4; ++l) {
            int i = tid + l * 256;
            int r = i >> 3, c4 = (i & 7) << 2;
            int site = site0 + r;
            float4 v = make_float4(0.f, 0.f, 0.f, 0.f);
            if (site < n) v = *(const float4*)&feats[(size_t)site * 256 + k0 + c4];
            sA[r * 33 + c4 + 0] = v.x; sA[r * 33 + c4 + 1] = v.y;
            sA[r * 33 + c4 + 2] = v.z; sA[r * 33 + c4 + 3] = v.w;
        }
#pragma unroll
        for (int l = 0; l < 2; ++l) {
            int i = tid + l * 256;
            int r = i >> 4, c4 = (i & 15) << 2;
            *(float4*)&sB[r * 64 + c4] = *(const float4*)&w1[(size_t)(k0 + r) * 64 + c4];
        }
        __syncthreads();
        mm32<33>(sA, sB, trow, tcol, acc);
        __syncthreads();
    }

    float sc[4], bi[4];
#pragma unroll
    for (int j = 0; j < 4; ++j) { sc[j] = s1[tcol + j]; bi[j] = b1[tcol + j]; }
#pragma unroll
    for (int i = 0; i < 8; ++i) {
        int site = site0 + trow + i;   // < NMAX always; OOB rows deterministic zeros
        float v0 = fmaxf(fmaf(acc[i][0], sc[0], bi[0]), 0.f);
        float v1 = fmaxf(fmaf(acc[i][1], sc[1], bi[1]), 0.f);
        float v2 = fmaxf(fmaf(acc[i][2], sc[2], bi[2]), 0.f);
        float v3 = fmaxf(fmaf(acc[i][3], sc[3], bi[3]), 0.f);
        uint32_t h0, l0, h1v, l1v;
        bsplit2(v0, v1, h0, l0);
        bsplit2(v2, v3, h1v, l1v);
        unsigned char* row = g_h1b + (size_t)site * 256;
        *(uint2*)(row + tcol * 2)       = make_uint2(h0, h1v);   // hi plane
        *(uint2*)(row + 128 + tcol * 2) = make_uint2(l0, l1v);   // lo plane
    }
}

// ---------------------------------------------------------------------------
// conv2 via mma.sync (3-term bf16 split), gather = pure copies from g_h1b.
#define LDA2 144   // smem A row stride in bytes

__global__ void __launch_bounds__(256) conv2_mma_kernel(
    const int* __restrict__ coords,
    const float* __restrict__ s2, const float* __restrict__ b2, int n)
{
    __shared__ int s_nbr[9 * 128];
    __shared__ float s_s2[64], s_b2[64];
    __shared__ __align__(16) unsigned char sA[2][128 * LDA2];  // hi, lo planes

    const int tid = threadIdx.x, wid = tid >> 5, lane = tid & 31;
    const int site0 = blockIdx.x * 128;

    if (tid < 64) { s_s2[tid] = s2[tid]; s_b2[tid] = b2[tid]; }
    if (tid < 128) {
#pragma unroll
        for (int t = 0; t < 9; ++t) s_nbr[t * 128 + tid] = -1;
        int site = site0 + tid;
        if (site < n) {
            int is64 = coords_is64(coords);
            int c = load_coord(coords, is64, site);
            int y = c / WGRID, x = c % WGRID;
#pragma unroll
            for (int t = 0; t < 9; ++t) {
                int ny = y + t / 3 - 1, nx = x + t % 3 - 1;
                if (ny >= 0 && ny < HGRID && nx >= 0 && nx < WGRID)
                    s_nbr[t * 128 + tid] = g_idx_map[ny * WGRID + nx];
            }
        }
    }
    __syncthreads();

    float acc[8][4];
#pragma unroll
    for (int t = 0; t < 8; ++t)
#pragma unroll
        for (int j = 0; j < 4; ++j) acc[t][j] = 0.f;

    const int rw = wid * 16;
    const int r2 = tid >> 1, half = tid & 1;   // 2 threads per row

#pragma unroll 1
    for (int tap = 0; tap < 9; ++tap) {
        // --- gather: copy 128B hi (half=0) or 128B lo (half=1) per row ---
        {
            int nb = s_nbr[tap * 128 + r2];
            const uint4* src =
                (const uint4*)(g_h1b + (size_t)(nb < 0 ? 0 : nb) * 256 + half * 128);
            uint4* dst = (uint4*)(&sA[half][0] + r2 * LDA2);
            uint4 z = make_uint4(0, 0, 0, 0);
#pragma unroll
            for (int g = 0; g < 8; ++g) dst[g] = (nb >= 0) ? src[g] : z;
        }
        __syncthreads();

        // --- mma: 4 k-chunks x 8 n-tiles x 3 split terms ---
        const uint4* wf = g_w2f + (size_t)tap * 1024 + lane;
#pragma unroll
        for (int kc = 0; kc < 4; ++kc) {
            uint32_t abase = (uint32_t)((rw + (lane >> 2)) * LDA2 +
                                        kc * 32 + (lane & 3) * 4);
            uint32_t ah[4], al[4];
            ah[0] = *(const uint32_t*)(&sA[0][0] + abase);
            ah[1] = *(const uint32_t*)(&sA[0][0] + abase + 8 * LDA2);
            ah[2] = *(const uint32_t*)(&sA[0][0] + abase + 16);
            ah[3] = *(const uint32_t*)(&sA[0][0] + abase + 8 * LDA2 + 16);
            al[0] = *(const uint32_t*)(&sA[1][0] + abase);
            al[1] = *(const uint32_t*)(&sA[1][0] + abase + 8 * LDA2);
            al[2] = *(const uint32_t*)(&sA[1][0] + abase + 16);
            al[3] = *(const uint32_t*)(&sA[1][0] + abase + 8 * LDA2 + 16);
#pragma unroll
            for (int nt = 0; nt < 8; ++nt) {
                uint4 b = wf[kc * 256 + nt * 32];
                mma16816(acc[nt], ah, b.x, b.y);
                mma16816(acc[nt], ah, b.z, b.w);
                mma16816(acc[nt], al, b.x, b.y);
            }
        }
        __syncthreads();
    }

    // --- epilogue: bn + relu, split to bf16 hi/lo, stage, coalesced write ---
    uint32_t* sh = (uint32_t*)&sA[0][0];   // 128 x 32 words, tight 128B rows
    uint32_t* sl = (uint32_t*)&sA[1][0];
    {
        int r0 = rw + (lane >> 2);
        int w0 = (lane & 3);
#pragma unroll
        for (int nt = 0; nt < 8; ++nt) {
            int n0 = nt * 8 + (lane & 3) * 2;
            int wc = nt * 4 + w0;
            float v0 = fmaxf(fmaf(acc[nt][0], s_s2[n0],     s_b2[n0]),     0.f);
            float v1 = fmaxf(fmaf(acc[nt][1], s_s2[n0 + 1], s_b2[n0 + 1]), 0.f);
            float v2 = fmaxf(fmaf(acc[nt][2], s_s2[n0],     s_b2[n0]),     0.f);
            float v3 = fmaxf(fmaf(acc[nt][3], s_s2[n0 + 1], s_b2[n0 + 1]), 0.f);
            uint32_t h, l;
            bsplit2(v0, v1, h, l);
            sh[r0 * 32 + wc] = h; sl[r0 * 32 + wc] = l;
            bsplit2(v2, v3, h, l);
            sh[(r0 + 8) * 32 + wc] = h; sl[(r0 + 8) * 32 + wc] = l;
        }
    }
    __syncthreads();
    {
        const uint4* src = (const uint4*)(&sA[half][0]) + r2 * 8;
        uint4* dst = (uint4*)(g_h2b + (size_t)(site0 + r2) * 256 + half * 128);
#pragma unroll
        for (int g = 0; g < 8; ++g) dst[g] = src[g];
    }
}

// ---------------------------------------------------------------------------
// conv3 via mma.sync: out = relu((h2 @ w3) * s3 + b3 + feats)
__global__ void __launch_bounds__(256) conv3_mma_kernel(
    const float* __restrict__ feats,
    const float* __restrict__ s3, const float* __restrict__ b3,
    float* __restrict__ out, int n)
{
    __shared__ float s_s3[64], s_b3[64];
    __shared__ __align__(16) unsigned char sA[2][128 * LDA2];

    const int tid = threadIdx.x, wid = tid >> 5, lane = tid & 31;
    const int site0 = blockIdx.x * 128;
    const int cb = blockIdx.y * 64;

    if (tid < 64) { s_s3[tid] = s3[cb + tid]; s_b3[tid] = b3[cb + tid]; }

    const int r2 = tid >> 1, half = tid & 1;
    {   // contiguous copy-in of h2 planes
        const uint4* src = (const uint4*)(g_h2b + (size_t)(site0 + r2) * 256 + half * 128);
        uint4* dst = (uint4*)(&sA[half][0] + r2 * LDA2);
#pragma unroll
        for (int g = 0; g < 8; ++g) dst[g] = src[g];
    }
    __syncthreads();

    float acc[8][4];
#pragma unroll
    for (int t = 0; t < 8; ++t)
#pragma unroll
        for (int j = 0; j < 4; ++j) acc[t][j] = 0.f;

    const int rw = wid * 16;
    const uint4* wf = g_w3f + (size_t)blockIdx.y * 1024 + lane;
#pragma unroll
    for (int kc = 0; kc < 4; ++kc) {
        uint32_t abase = (uint32_t)((rw + (lane >> 2)) * LDA2 +
                                    kc * 32 + (lane & 3) * 4);
        uint32_t ah[4], al[4];
        ah[0] = *(const uint32_t*)(&sA[0][0] + abase);
        ah[1] = *(const uint32_t*)(&sA[0][0] + abase + 8 * LDA2);
        ah[2] = *(const uint32_t*)(&sA[0][0] + abase + 16);
        ah[3] = *(const uint32_t*)(&sA[0][0] + abase + 8 * LDA2 + 16);
        al[0] = *(const uint32_t*)(&sA[1][0] + abase);
        al[1] = *(const uint32_t*)(&sA[1][0] + abase + 8 * LDA2);
        al[2] = *(const uint32_t*)(&sA[1][0] + abase + 16);
        al[3] = *(const uint32_t*)(&sA[1][0] + abase + 8 * LDA2 + 16);
#pragma unroll
        for (int nt = 0; nt < 8; ++nt) {
            uint4 b = wf[kc * 256 + nt * 32];
            mma16816(acc[nt], ah, b.x, b.y);
            mma16816(acc[nt], ah, b.z, b.w);
            mma16816(acc[nt], al, b.x, b.y);
        }
    }
    __syncthreads();

    // stage bn result (pre-residual) as f32, then coalesced residual+relu+write
    float* stg = (float*)&sA[0][0];   // 128 x 64 f32 = 32KB (sA is 36KB)
    {
        int r0 = rw + (lane >> 2);
#pragma unroll
        for (int nt = 0; nt < 8; ++nt) {
            int n0 = nt * 8 + (lane & 3) * 2;
            stg[r0 * 64 + n0]           = fmaf(acc[nt][0], s_s3[n0],     s_b3[n0]);
            stg[r0 * 64 + n0 + 1]       = fmaf(acc[nt][1], s_s3[n0 + 1], s_b3[n0 + 1]);
            stg[(r0 + 8) * 64 + n0]     = fmaf(acc[nt][2], s_s3[n0],     s_b3[n0]);
            stg[(r0 + 8) * 64 + n0 + 1] = fmaf(acc[nt][3], s_s3[n0 + 1], s_b3[n0 + 1]);
        }
    }
    __syncthreads();
    {
        int site = site0 + r2;
        if (site < n) {
            const float4* idn = (const float4*)&feats[(size_t)site * 256 + cb + half * 32];
            const float4* s   = (const float4*)(stg + r2 * 64 + half * 32);
            float4* dst = (float4*)&out[(size_t)site * 256 + cb + half * 32];
#pragma unroll
            for (int j = 0; j < 8; ++j) {
                float4 a = s[j], b = idn[j], o;
                o.x = fmaxf(a.x + b.x, 0.f);
                o.y = fmaxf(a.y + b.y, 0.f);
                o.z = fmaxf(a.z + b.z, 0.f);
                o.w = fmaxf(a.w + b.w, 0.f);
                dst[j] = o;
            }
        }
    }
}

// ---------------------------------------------------------------------------
extern "C" void kernel_launch(void* const* d_in, const int* in_sizes, int n_in,
                              void* d_out, int out_size) {
    const float* feats  = (const float*)d_in[0];
    const int*   coords = (const int*)d_in[1];
    const float* w1     = (const float*)d_in[2];
    const float* w2     = (const float*)d_in[3];
    const float* w3     = (const float*)d_in[4];
    const float* s1     = (const float*)d_in[5];
    const float* b1     = (const float*)d_in[6];
    const float* s2     = (const float*)d_in[7];
    const float* b2     = (const float*)d_in[8];
    const float* s3     = (const float*)d_in[9];
    const float* b3     = (const float*)d_in[10];
    float* out = (float*)d_out;

    const int n = in_sizes[0] / 256;
    const int tiles = (n + 127) / 128;

    clear_map_kernel<<<(HGRID * WGRID + 255) / 256, 256>>>();
    scatter_map_kernel<<<(n + 255) / 256, 256>>>(coords, n);
    prep_w2f_kernel<<<(9 * 4 * 8 * 32 + 255) / 256, 256>>>(w2);
    prep_w3f_kernel<<<(4 * 4 * 8 * 32 + 255) / 256, 256>>>(w3);
    conv1_kernel<<<tiles, 256>>>(feats, w1, s1, b1, n);
    conv2_mma_kernel<<<tiles, 256>>>(coords, s2, b2, n);
    conv3_mma_kernel<<<dim3(tiles, 4), 256>>>(feats, s3, b3, out, n);
}

// round 5
// speedup vs baseline: 1.1247x; 1.1247x over previous
#include <cuda_runtime.h>
#include <cuda_bf16.h>
#include <cstdint>

#define HGRID 768
#define WGRID 768
#define NMAX  200064   // 1563 * 128

// Scratch in __device__ globals (no allocation allowed).
__device__ int g_idx_map[HGRID * WGRID];
// h1 as interleaved bf16 split planes: per row {128B hi, 128B lo}
__device__ __align__(16) unsigned char g_h1b[(size_t)NMAX * 256];
// w2 B fragments: [tap][kc(4)][nt(8)][lane(32)] uint4 {bhi0,bhi1,blo0,blo1}
__device__ uint4 g_w2f[9 * 4 * 8 * 32];
// w3 B fragments: [cb(4)][kc(4)][nt(8)][lane(32)]
__device__ uint4 g_w3f[4 * 4 * 8 * 32];

// ---------------------------------------------------------------------------
__device__ __forceinline__ int coords_is64(const int* c) { return c[1] == 0; }
__device__ __forceinline__ int load_coord(const int* c, int is64, int i) {
    return is64 ? c[2 * i] : c[i];
}
__device__ __forceinline__ void bsplit2(float a, float b, uint32_t& hi, uint32_t& lo) {
    __nv_bfloat16 ah = __float2bfloat16(a);
    __nv_bfloat16 bh = __float2bfloat16(b);
    float ar = a - __bfloat162float(ah);
    float br = b - __bfloat162float(bh);
    __nv_bfloat162 h; h.x = ah; h.y = bh;
    __nv_bfloat162 l; l.x = __float2bfloat16(ar); l.y = __float2bfloat16(br);
    hi = *reinterpret_cast<uint32_t*>(&h);
    lo = *reinterpret_cast<uint32_t*>(&l);
}

// mma.sync m16n8k16 bf16 -> f32 accumulate
__device__ __forceinline__ void mma16816(float c[4], const uint32_t a[4],
                                         uint32_t b0, uint32_t b1) {
    asm volatile(
        "mma.sync.aligned.m16n8k16.row.col.f32.bf16.bf16.f32 "
        "{%0,%1,%2,%3}, {%4,%5,%6,%7}, {%8,%9}, {%0,%1,%2,%3};"
        : "+f"(c[0]), "+f"(c[1]), "+f"(c[2]), "+f"(c[3])
        : "r"(a[0]), "r"(a[1]), "r"(a[2]), "r"(a[3]), "r"(b0), "r"(b1));
}

// ---------------------------------------------------------------------------
__global__ void clear_map_kernel() {
    int i = blockIdx.x * blockDim.x + threadIdx.x;
    if (i < HGRID * WGRID) g_idx_map[i] = -1;
}
__global__ void scatter_map_kernel(const int* __restrict__ coords, int n) {
    int i = blockIdx.x * blockDim.x + threadIdx.x;
    int is64 = coords_is64(coords);
    if (i < n) g_idx_map[load_coord(coords, is64, i)] = i;
}

// w2 [9][64 k][64 n] -> per-lane B fragments (hi/lo bf16 split).
__global__ void prep_w2f_kernel(const float* __restrict__ w2) {
    int i = blockIdx.x * blockDim.x + threadIdx.x;
    if (i >= 9 * 4 * 8 * 32) return;
    int lane = i & 31, nt = (i >> 5) & 7, kc = (i >> 8) & 3, tap = i >> 10;
    int n  = nt * 8 + (lane >> 2);
    int k0 = kc * 16 + (lane & 3) * 2;
    uint32_t hi[2], lo[2];
#pragma unroll
    for (int j = 0; j < 2; ++j) {
        int k = k0 + j * 8;
        bsplit2(w2[tap * 4096 + k * 64 + n], w2[tap * 4096 + (k + 1) * 64 + n],
                hi[j], lo[j]);
    }
    g_w2f[i] = make_uint4(hi[0], hi[1], lo[0], lo[1]);
}

// w3 [64 k][256 n] -> per-lane B fragments per 64-col block cb.
__global__ void prep_w3f_kernel(const float* __restrict__ w3) {
    int i = blockIdx.x * blockDim.x + threadIdx.x;
    if (i >= 4 * 4 * 8 * 32) return;
    int lane = i & 31, nt = (i >> 5) & 7, kc = (i >> 8) & 3, cb = i >> 10;
    int n  = cb * 64 + nt * 8 + (lane >> 2);
    int k0 = kc * 16 + (lane & 3) * 2;
    uint32_t hi[2], lo[2];
#pragma unroll
    for (int j = 0; j < 2; ++j) {
        int k = k0 + j * 8;
        bsplit2(w3[k * 256 + n], w3[(k + 1) * 256 + n], hi[j], lo[j]);
    }
    g_w3f[i] = make_uint4(hi[0], hi[1], lo[0], lo[1]);
}

// ---------------------------------------------------------------------------
// FFMA micro-kernel (conv1)
template <int LDA>
__device__ __forceinline__ void mm32(const float* __restrict__ sA,
                                     const float* __restrict__ sB,
                                     int trow, int tcol, float acc[8][4]) {
#pragma unroll
    for (int k = 0; k < 32; ++k) {
        float4 b = *(const float4*)(sB + k * 64 + tcol);
#pragma unroll
        for (int i = 0; i < 8; ++i) {
            float a = sA[(trow + i) * LDA + k];
            acc[i][0] = fmaf(a, b.x, acc[i][0]);
            acc[i][1] = fmaf(a, b.y, acc[i][1]);
            acc[i][2] = fmaf(a, b.z, acc[i][2]);
            acc[i][3] = fmaf(a, b.w, acc[i][3]);
        }
    }
}

// conv1: h1 = relu((feats @ w1) * s1 + b1) -> bf16 hi/lo planes
__global__ void __launch_bounds__(256) conv1_kernel(
    const float* __restrict__ feats, const float* __restrict__ w1,
    const float* __restrict__ s1, const float* __restrict__ b1, int n)
{
    __shared__ __align__(16) float sA[128 * 33];
    __shared__ __align__(16) float sB[32 * 64];
    const int tid = threadIdx.x;
    const int site0 = blockIdx.x * 128;
    const int trow = (tid >> 4) << 3;
    const int tcol = (tid & 15) << 2;

    float acc[8][4];
#pragma unroll
    for (int i = 0; i < 8; ++i)
#pragma unroll
        for (int j = 0; j < 4; ++j) acc[i][j] = 0.f;

#pragma unroll 1
    for (int k0 = 0; k0 < 256; k0 += 32) {
#pragma unroll
        for (int l = 0; l < 4; ++l) {
            int i = tid + l * 256;
            int r = i >> 3, c4 = (i & 7) << 2;
            int site = site0 + r;
            float4 v = make_float4(0.f, 0.f, 0.f, 0.f);
            if (site < n) v = *(const float4*)&feats[(size_t)site * 256 + k0 + c4];
            sA[r * 33 + c4 + 0] = v.x; sA[r * 33 + c4 + 1] = v.y;
            sA[r * 33 + c4 + 2] = v.z; sA[r * 33 + c4 + 3] = v.w;
        }
#pragma unroll
        for (int l = 0; l < 2; ++l) {
            int i = tid + l * 256;
            int r = i >> 4, c4 = (i & 15) << 2;
            *(float4*)&sB[r * 64 + c4] = *(const float4*)&w1[(size_t)(k0 + r) * 64 + c4];
        }
        __syncthreads();
        mm32<33>(sA, sB, trow, tcol, acc);
        __syncthreads();
    }

    float sc[4], bi[4];
#pragma unroll
    for (int j = 0; j < 4; ++j) { sc[j] = s1[tcol + j]; bi[j] = b1[tcol + j]; }
#pragma unroll
    for (int i = 0; i < 8; ++i) {
        int site = site0 + trow + i;   // < NMAX always; OOB rows never read back
        float v0 = fmaxf(fmaf(acc[i][0], sc[0], bi[0]), 0.f);
        float v1 = fmaxf(fmaf(acc[i][1], sc[1], bi[1]), 0.f);
        float v2 = fmaxf(fmaf(acc[i][2], sc[2], bi[2]), 0.f);
        float v3 = fmaxf(fmaf(acc[i][3], sc[3], bi[3]), 0.f);
        uint32_t h0, l0, h1v, l1v;
        bsplit2(v0, v1, h0, l0);
        bsplit2(v2, v3, h1v, l1v);
        unsigned char* row = g_h1b + (size_t)site * 256;
        *(uint2*)(row + tcol * 2)       = make_uint2(h0, h1v);   // hi plane
        *(uint2*)(row + 128 + tcol * 2) = make_uint2(l0, l1v);   // lo plane
    }
}

// ---------------------------------------------------------------------------
// FUSED conv2 + conv3:
//   h2 = relu(sparse3x3(h1) * s2 + b2)   (registers only, never stored)
//   out = relu((h2 @ w3) * s3 + b3 + feats)
// The m16n8 C-fragment of GEMM-1 IS the m16k16 A-fragment of GEMM-2
// (n-tile pair (2kc, 2kc+1) -> k-chunk kc), so h2 stays in registers.
#define LDA2 144   // smem A row stride in bytes

__global__ void __launch_bounds__(256) conv23_kernel(
    const int* __restrict__ coords,
    const float* __restrict__ s2, const float* __restrict__ b2,
    const float* __restrict__ feats,
    const float* __restrict__ s3, const float* __restrict__ b3,
    float* __restrict__ out, int n)
{
    __shared__ int s_nbr[9 * 128];
    __shared__ float s_s2[64], s_b2[64];
    __shared__ float s_s3[256], s_b3[256];
    __shared__ __align__(16) unsigned char sA[2][128 * LDA2];  // hi, lo planes

    const int tid = threadIdx.x, wid = tid >> 5, lane = tid & 31;
    const int site0 = blockIdx.x * 128;

    if (tid < 64) { s_s2[tid] = s2[tid]; s_b2[tid] = b2[tid]; }
    s_s3[tid] = s3[tid]; s_b3[tid] = b3[tid];
    if (tid < 128) {
#pragma unroll
        for (int t = 0; t < 9; ++t) s_nbr[t * 128 + tid] = -1;
        int site = site0 + tid;
        if (site < n) {
            int is64 = coords_is64(coords);
            int c = load_coord(coords, is64, site);
            int y = c / WGRID, x = c % WGRID;
#pragma unroll
            for (int t = 0; t < 9; ++t) {
                int ny = y + t / 3 - 1, nx = x + t % 3 - 1;
                if (ny >= 0 && ny < HGRID && nx >= 0 && nx < WGRID)
                    s_nbr[t * 128 + tid] = g_idx_map[ny * WGRID + nx];
            }
        }
    }
    __syncthreads();

    float acc[8][4];
#pragma unroll
    for (int t = 0; t < 8; ++t)
#pragma unroll
        for (int j = 0; j < 4; ++j) acc[t][j] = 0.f;

    const int rw = wid * 16;
    const int r2 = tid >> 1, half = tid & 1;   // 2 threads per row

    // ---------------- conv2: 9-tap sparse 3x3 accumulation ----------------
#pragma unroll 1
    for (int tap = 0; tap < 9; ++tap) {
        {   // gather: copy 128B hi (half=0) or 128B lo (half=1) per row
            int nb = s_nbr[tap * 128 + r2];
            const uint4* src =
                (const uint4*)(g_h1b + (size_t)(nb < 0 ? 0 : nb) * 256 + half * 128);
            uint4* dst = (uint4*)(&sA[half][0] + r2 * LDA2);
            uint4 z = make_uint4(0, 0, 0, 0);
#pragma unroll
            for (int g = 0; g < 8; ++g) dst[g] = (nb >= 0) ? src[g] : z;
        }
        __syncthreads();

        const uint4* wf = g_w2f + (size_t)tap * 1024 + lane;
#pragma unroll
        for (int kc = 0; kc < 4; ++kc) {
            uint32_t abase = (uint32_t)((rw + (lane >> 2)) * LDA2 +
                                        kc * 32 + (lane & 3) * 4);
            uint32_t ah[4], al[4];
            ah[0] = *(const uint32_t*)(&sA[0][0] + abase);
            ah[1] = *(const uint32_t*)(&sA[0][0] + abase + 8 * LDA2);
            ah[2] = *(const uint32_t*)(&sA[0][0] + abase + 16);
            ah[3] = *(const uint32_t*)(&sA[0][0] + abase + 8 * LDA2 + 16);
            al[0] = *(const uint32_t*)(&sA[1][0] + abase);
            al[1] = *(const uint32_t*)(&sA[1][0] + abase + 8 * LDA2);
            al[2] = *(const uint32_t*)(&sA[1][0] + abase + 16);
            al[3] = *(const uint32_t*)(&sA[1][0] + abase + 8 * LDA2 + 16);
#pragma unroll
            for (int nt = 0; nt < 8; ++nt) {
                uint4 b = wf[kc * 256 + nt * 32];
                mma16816(acc[nt], ah, b.x, b.y);
                mma16816(acc[nt], ah, b.z, b.w);
                mma16816(acc[nt], al, b.x, b.y);
            }
        }
        __syncthreads();
    }

    // ------- bn2 + relu in registers; repackage C-frags as A-frags --------
    uint32_t fh[4][4], fl[4][4];   // [k-chunk][reg], hi and lo planes
    {
        const int n0 = (lane & 3) * 2;
#pragma unroll
        for (int kc = 0; kc < 4; ++kc) {
#pragma unroll
            for (int p = 0; p < 2; ++p) {          // n-tile pair member
                int nt = 2 * kc + p;
                int c0 = nt * 8 + n0;
                float v0 = fmaxf(fmaf(acc[nt][0], s_s2[c0],     s_b2[c0]),     0.f);
                float v1 = fmaxf(fmaf(acc[nt][1], s_s2[c0 + 1], s_b2[c0 + 1]), 0.f);
                float v2 = fmaxf(fmaf(acc[nt][2], s_s2[c0],     s_b2[c0]),     0.f);
                float v3 = fmaxf(fmaf(acc[nt][3], s_s2[c0 + 1], s_b2[c0 + 1]), 0.f);
                bsplit2(v0, v1, fh[kc][2 * p],     fl[kc][2 * p]);       // rows r0
                bsplit2(v2, v3, fh[kc][2 * p + 1], fl[kc][2 * p + 1]);   // rows r0+8
            }
        }
    }

    // ---------------- conv3: 4 column blocks of 64, from registers --------
    float* stg = (float*)&sA[0][0];   // 128 x 64 f32 staging = 32KB
#pragma unroll 1
    for (int cb = 0; cb < 4; ++cb) {
        float acc2[8][4];
#pragma unroll
        for (int t = 0; t < 8; ++t)
#pragma unroll
            for (int j = 0; j < 4; ++j) acc2[t][j] = 0.f;

        const uint4* wf = g_w3f + (size_t)cb * 1024 + lane;
#pragma unroll
        for (int kc = 0; kc < 4; ++kc) {
#pragma unroll
            for (int nt = 0; nt < 8; ++nt) {
                uint4 b = wf[kc * 256 + nt * 32];
                mma16816(acc2[nt], fh[kc], b.x, b.y);
                mma16816(acc2[nt], fh[kc], b.z, b.w);
                mma16816(acc2[nt], fl[kc], b.x, b.y);
            }
        }
        __syncthreads();   // prev iteration's stg reads done
        {
            int r0 = rw + (lane >> 2);
            int n0 = (lane & 3) * 2;
#pragma unroll
            for (int nt = 0; nt < 8; ++nt) {
                int c  = nt * 8 + n0;
                int cg = cb * 64 + c;
                stg[r0 * 64 + c]           = fmaf(acc2[nt][0], s_s3[cg],     s_b3[cg]);
                stg[r0 * 64 + c + 1]       = fmaf(acc2[nt][1], s_s3[cg + 1], s_b3[cg + 1]);
                stg[(r0 + 8) * 64 + c]     = fmaf(acc2[nt][2], s_s3[cg],     s_b3[cg]);
                stg[(r0 + 8) * 64 + c + 1] = fmaf(acc2[nt][3], s_s3[cg + 1], s_b3[cg + 1]);
            }
        }
        __syncthreads();
        {
            int site = site0 + r2;
            if (site < n) {
                const float4* idn =
                    (const float4*)&feats[(size_t)site * 256 + cb * 64 + half * 32];
                const float4* s = (const float4*)(stg + r2 * 64 + half * 32);
                float4* dst = (float4*)&out[(size_t)site * 256 + cb * 64 + half * 32];
#pragma unroll
                for (int j = 0; j < 8; ++j) {
                    float4 a = s[j], b = idn[j], o;
                    o.x = fmaxf(a.x + b.x, 0.f);
                    o.y = fmaxf(a.y + b.y, 0.f);
                    o.z = fmaxf(a.z + b.z, 0.f);
                    o.w = fmaxf(a.w + b.w, 0.f);
                    dst[j] = o;
                }
            }
        }
    }
}

// ---------------------------------------------------------------------------
extern "C" void kernel_launch(void* const* d_in, const int* in_sizes, int n_in,
                              void* d_out, int out_size) {
    const float* feats  = (const float*)d_in[0];
    const int*   coords = (const int*)d_in[1];
    const float* w1     = (const float*)d_in[2];
    const float* w2     = (const float*)d_in[3];
    const float* w3     = (const float*)d_in[4];
    const float* s1     = (const float*)d_in[5];
    const float* b1     = (const float*)d_in[6];
    const float* s2     = (const float*)d_in[7];
    const float* b2     = (const float*)d_in[8];
    const float* s3     = (const float*)d_in[9];
    const float* b3     = (const float*)d_in[10];
    float* out = (float*)d_out;

    const int n = in_sizes[0] / 256;
    const int tiles = (n + 127) / 128;

    clear_map_kernel<<<(HGRID * WGRID + 255) / 256, 256>>>();
    scatter_map_kernel<<<(n + 255) / 256, 256>>>(coords, n);
    prep_w2f_kernel<<<(9 * 4 * 8 * 32 + 255) / 256, 256>>>(w2);
    prep_w3f_kernel<<<(4 * 4 * 8 * 32 + 255) / 256, 256>>>(w3);
    conv1_kernel<<<tiles, 256>>>(feats, w1, s1, b1, n);
    conv23_kernel<<<tiles, 256>>>(coords, s2, b2, feats, s3, b3, out, n);
}